// round 3
// baseline (speedup 1.0000x reference)
#include <cuda_runtime.h>

// Problem constants
#define M_DIM 4096   // B*T = 8*512
#define N_DIM 1024   // D
#define K_DIM 1024   // D
#define NUM_OPS 8

#define BM 128
#define BN 128
#define BK 16
#define TM 8
#define TN 8
// threads = (BM/TM)*(BN/TN) = 16*16 = 256

__global__ __launch_bounds__(256, 2)
void mixed_op_gemm_kernel(const float* __restrict__ x,
                          const float* __restrict__ W,
                          const float* __restrict__ b,
                          const float* __restrict__ logits,
                          const float* __restrict__ u,
                          float* __restrict__ out)
{
    __shared__ float As[BK][BM];   // transposed A tile
    __shared__ float Bs[BK][BN];
    __shared__ int s_idx;

    const int tid = threadIdx.x;

    // --- op selection: argmax(log_softmax(logits) + gumbel) == argmax(logits + gumbel)
    if (tid == 0) {
        float best = -1e30f;
        int bi = 0;
        #pragma unroll
        for (int i = 0; i < NUM_OPS; i++) {
            float g = -logf(-logf(u[i]));
            float v = logits[i] + g;
            if (v > best) { best = v; bi = i; }
        }
        s_idx = bi;
    }
    __syncthreads();
    const int idx = s_idx;
    const float* __restrict__ Wp = W + (size_t)idx * K_DIM * N_DIM;
    const float* __restrict__ bp = b + idx * N_DIM;

    const int cRow = blockIdx.y;   // M tile index
    const int cCol = blockIdx.x;   // N tile index

    // thread tile coordinates
    const int tCol = tid % (BN / TN);   // 0..15
    const int tRow = tid / (BN / TN);   // 0..15

    // global-load coordinates (float4 vectorized)
    const int aRow = tid / (BK / 4);          // 0..63 (stride 64)
    const int aCol = (tid % (BK / 4)) * 4;    // 0,4,8,12
    const int bRow = tid / (BN / 4);          // 0..7 (stride 8)
    const int bCol = (tid % (BN / 4)) * 4;    // 0..124

    const float* __restrict__ Ag = x + (size_t)cRow * BM * K_DIM;

    float acc[TM][TN] = {};
    float regM[TM], regN[TN];

    for (int k0 = 0; k0 < K_DIM; k0 += BK) {
        // Load A tile (BM x BK), transpose into As[BK][BM]
        #pragma unroll
        for (int r = 0; r < BM; r += 64) {
            float4 v = *reinterpret_cast<const float4*>(
                Ag + (size_t)(aRow + r) * K_DIM + k0 + aCol);
            As[aCol + 0][aRow + r] = v.x;
            As[aCol + 1][aRow + r] = v.y;
            As[aCol + 2][aRow + r] = v.z;
            As[aCol + 3][aRow + r] = v.w;
        }
        // Load B tile (BK x BN)
        #pragma unroll
        for (int r = 0; r < BK; r += 8) {
            float4 v = *reinterpret_cast<const float4*>(
                Wp + (size_t)(k0 + bRow + r) * N_DIM + cCol * BN + bCol);
            *reinterpret_cast<float4*>(&Bs[bRow + r][bCol]) = v;
        }
        __syncthreads();

        #pragma unroll
        for (int kk = 0; kk < BK; kk++) {
            #pragma unroll
            for (int i = 0; i < TM; i++) regM[i] = As[kk][tRow * TM + i];
            #pragma unroll
            for (int j = 0; j < TN; j++) regN[j] = Bs[kk][tCol * TN + j];
            #pragma unroll
            for (int i = 0; i < TM; i++)
                #pragma unroll
                for (int j = 0; j < TN; j++)
                    acc[i][j] += regM[i] * regN[j];
        }
        __syncthreads();
    }

    // Epilogue: add bias, store
    #pragma unroll
    for (int i = 0; i < TM; i++) {
        const int row = cRow * BM + tRow * TM + i;
        #pragma unroll
        for (int j = 0; j < TN; j += 4) {
            const int col = cCol * BN + tCol * TN + j;
            float4 v;
            v.x = acc[i][j + 0] + bp[col + 0];
            v.y = acc[i][j + 1] + bp[col + 1];
            v.z = acc[i][j + 2] + bp[col + 2];
            v.w = acc[i][j + 3] + bp[col + 3];
            *reinterpret_cast<float4*>(out + (size_t)row * N_DIM + col) = v;
        }
    }
}

extern "C" void kernel_launch(void* const* d_in, const int* in_sizes, int n_in,
                              void* d_out, int out_size) {
    const float* x      = (const float*)d_in[0];  // [8,512,1024]
    const float* W      = (const float*)d_in[1];  // [8,1024,1024]
    const float* b      = (const float*)d_in[2];  // [8,1024]
    const float* logits = (const float*)d_in[3];  // [8]
    const float* u      = (const float*)d_in[4];  // [8]
    float* out          = (float*)d_out;          // [8,512,1024]

    dim3 grid(N_DIM / BN, M_DIM / BM);  // (8, 32)
    dim3 block(256);
    mixed_op_gemm_kernel<<<grid, block>>>(x, W, b, logits, u, out);
}

// round 7
// speedup vs baseline: 2.3539x; 2.3539x over previous
#include <cuda_runtime.h>
#include <cuda_bf16.h>
#include <cstdint>

#define M_DIM 4096
#define N_DIM 1024
#define K_DIM 1024
#define NUM_OPS 8

#define BM 128
#define BN 128
#define BK 32
#define NSTEPS (K_DIM / BK)   // 32

// smem layout (bf16 elements), pitched rows so ldmatrix is conflict-free:
//  A tiles: 128 rows x APITCH, use cols 0..31   (pitch 80B = 5 x 16B, odd -> cf)
//  B tiles:  32 rows x BPITCH, use cols 0..127  (pitch 272B = 17 x 16B, odd -> cf)
#define APITCH 40
#define BPITCH 136
#define A_BYTES (128 * APITCH * 2)            // 10240
#define B_BYTES (32 * BPITCH * 2)             // 8704
#define BUF_BYTES (2 * A_BYTES + 2 * B_BYTES) // 37888  (Ah, Al, Bh, Bl)
#define SMEM_TOTAL (2 * BUF_BYTES)            // 75776

// ---------------- PTX helpers (baseline ISA only — no 'a' features) ----------
__device__ __forceinline__ void ldsm_x4(uint32_t* r, uint32_t addr) {
    asm volatile("ldmatrix.sync.aligned.m8n8.x4.shared.b16 {%0,%1,%2,%3}, [%4];"
        : "=r"(r[0]), "=r"(r[1]), "=r"(r[2]), "=r"(r[3]) : "r"(addr));
}
__device__ __forceinline__ void ldsm_x4_t(uint32_t* r, uint32_t addr) {
    asm volatile("ldmatrix.sync.aligned.m8n8.x4.trans.shared.b16 {%0,%1,%2,%3}, [%4];"
        : "=r"(r[0]), "=r"(r[1]), "=r"(r[2]), "=r"(r[3]) : "r"(addr));
}
__device__ __forceinline__ void mma_bf16(float* d, const uint32_t* a,
                                         const uint32_t* b) {
    asm volatile(
        "mma.sync.aligned.m16n8k16.row.col.f32.bf16.bf16.f32 "
        "{%0,%1,%2,%3}, {%4,%5,%6,%7}, {%8,%9}, {%0,%1,%2,%3};"
        : "+f"(d[0]), "+f"(d[1]), "+f"(d[2]), "+f"(d[3])
        : "r"(a[0]), "r"(a[1]), "r"(a[2]), "r"(a[3]), "r"(b[0]), "r"(b[1]));
}
__device__ __forceinline__ uint32_t bf2_bits(__nv_bfloat162 h) {
    return *reinterpret_cast<uint32_t*>(&h);
}
// split one float4 into hi/lo bf16x2 pairs
__device__ __forceinline__ void split4(float4 v, uint2& hi, uint2& lo) {
    __nv_bfloat162 h01 = __floats2bfloat162_rn(v.x, v.y);
    __nv_bfloat162 h23 = __floats2bfloat162_rn(v.z, v.w);
    float r0 = v.x - __bfloat162float(h01.x);
    float r1 = v.y - __bfloat162float(h01.y);
    float r2 = v.z - __bfloat162float(h23.x);
    float r3 = v.w - __bfloat162float(h23.y);
    __nv_bfloat162 l01 = __floats2bfloat162_rn(r0, r1);
    __nv_bfloat162 l23 = __floats2bfloat162_rn(r2, r3);
    hi = make_uint2(bf2_bits(h01), bf2_bits(h23));
    lo = make_uint2(bf2_bits(l01), bf2_bits(l23));
}

// ---------------- kernel ----------------
__global__ void __launch_bounds__(256, 1)
mixed_op_hmma_kernel(const float* __restrict__ x,
                     const float* __restrict__ W,
                     const float* __restrict__ b,
                     const float* __restrict__ logits,
                     const float* __restrict__ u,
                     float* __restrict__ out)
{
    extern __shared__ char smem[];
    __shared__ int s_idx;

    const int tid = threadIdx.x;
    const int w = tid >> 5;
    const int l = tid & 31;

    // --- op selection: argmax(logits + gumbel(u)) ---
    if (tid == 0) {
        float best = -1e30f; int bi = 0;
        #pragma unroll
        for (int i = 0; i < NUM_OPS; i++) {
            float v = logits[i] - logf(-logf(u[i]));
            if (v > best) { best = v; bi = i; }
        }
        s_idx = bi;
    }
    __syncthreads();
    const int idx = s_idx;

    const int m0 = blockIdx.y * BM;
    const int n0 = blockIdx.x * BN;
    const float* __restrict__ Wp = W + (size_t)idx * K_DIM * N_DIM + n0;
    const float* __restrict__ bp = b + idx * N_DIM;

    const uint32_t sb = (uint32_t)__cvta_generic_to_shared(smem);

    // gmem load coords
    const int arow = tid >> 3;          // 0..31 (4 passes of 32 rows)
    const int acol = (tid & 7) * 4;     // float4 within 32-float A row
    const int brow = tid >> 5;          // 0..7 (4 passes of 8 rows)
    const int bcol = (tid & 31) * 4;    // float4 within 128-float B row

    // warp tiling: 4 (m) x 2 (n); warp tile 32m x 64n
    const int warp_m = (w & 3) * 32;
    const int warp_n = (w >> 2) * 64;

    float4 aR[4], bR[4];
    float acc[2][8][4] = {};            // [mi][nj][frag]

    // prologue: tile 0
    #pragma unroll
    for (int p = 0; p < 4; p++)
        aR[p] = *reinterpret_cast<const float4*>(
            x + (size_t)(m0 + arow + 32 * p) * K_DIM + acol);
    #pragma unroll
    for (int p = 0; p < 4; p++)
        bR[p] = *reinterpret_cast<const float4*>(
            Wp + (size_t)(brow + 8 * p) * N_DIM + bcol);

    for (int s = 0; s < NSTEPS; s++) {
        const int buf = s & 1;
        char* Ah = smem + buf * BUF_BYTES;
        char* Al = Ah + A_BYTES;
        char* Bh = Al + A_BYTES;
        char* Bl = Bh + B_BYTES;

        // convert prefetched regs -> smem[buf]
        #pragma unroll
        for (int p = 0; p < 4; p++) {
            uint2 hi, lo;
            split4(aR[p], hi, lo);
            const int off = (arow + 32 * p) * (APITCH * 2) + acol * 2;
            *reinterpret_cast<uint2*>(Ah + off) = hi;
            *reinterpret_cast<uint2*>(Al + off) = lo;
        }
        #pragma unroll
        for (int p = 0; p < 4; p++) {
            uint2 hi, lo;
            split4(bR[p], hi, lo);
            const int off = (brow + 8 * p) * (BPITCH * 2) + bcol * 2;
            *reinterpret_cast<uint2*>(Bh + off) = hi;
            *reinterpret_cast<uint2*>(Bl + off) = lo;
        }
        __syncthreads();

        // issue next tile's LDGs (hidden under compute)
        if (s + 1 < NSTEPS) {
            const int k0 = (s + 1) * BK;
            #pragma unroll
            for (int p = 0; p < 4; p++)
                aR[p] = *reinterpret_cast<const float4*>(
                    x + (size_t)(m0 + arow + 32 * p) * K_DIM + k0 + acol);
            #pragma unroll
            for (int p = 0; p < 4; p++)
                bR[p] = *reinterpret_cast<const float4*>(
                    Wp + (size_t)(k0 + brow + 8 * p) * N_DIM + bcol);
        }

        // compute: 2 k16 substeps
        const uint32_t AhB = sb + buf * BUF_BYTES;
        const uint32_t AlB = AhB + A_BYTES;
        const uint32_t BhB = AlB + A_BYTES;
        const uint32_t BlB = BhB + B_BYTES;

        #pragma unroll
        for (int ks = 0; ks < 2; ks++) {
            uint32_t afh[2][4], afl[2][4];   // [mi][4]
            uint32_t bfh[4][4], bfl[4][4];   // [njp][4]

            #pragma unroll
            for (int mi = 0; mi < 2; mi++) {
                const uint32_t aoff =
                    (uint32_t)((warp_m + mi * 16 + (l & 15)) * (APITCH * 2) +
                               (ks * 16 + (l >> 4) * 8) * 2);
                ldsm_x4(afh[mi], AhB + aoff);
                ldsm_x4(afl[mi], AlB + aoff);
            }
            #pragma unroll
            for (int njp = 0; njp < 4; njp++) {
                const uint32_t boff =
                    (uint32_t)((ks * 16 + (l & 15)) * (BPITCH * 2) +
                               (warp_n + njp * 16 + (l >> 4) * 8) * 2);
                ldsm_x4_t(bfh[njp], BhB + boff);
                ldsm_x4_t(bfl[njp], BlB + boff);
            }

            #pragma unroll
            for (int mi = 0; mi < 2; mi++)
                #pragma unroll
                for (int njp = 0; njp < 4; njp++)
                    #pragma unroll
                    for (int h = 0; h < 2; h++) {
                        const int nj = njp * 2 + h;
                        mma_bf16(acc[mi][nj], afh[mi], &bfh[njp][h * 2]); // Ah*Bh
                        mma_bf16(acc[mi][nj], afh[mi], &bfl[njp][h * 2]); // Ah*Bl
                        mma_bf16(acc[mi][nj], afl[mi], &bfh[njp][h * 2]); // Al*Bh
                    }
        }
        __syncthreads();
    }

    // --- epilogue: bias add + store ---
    #pragma unroll
    for (int mi = 0; mi < 2; mi++) {
        const int r0 = m0 + warp_m + mi * 16 + (l >> 2);
        #pragma unroll
        for (int nj = 0; nj < 8; nj++) {
            const int col = n0 + warp_n + nj * 8 + (l & 3) * 2;
            const float b0 = __ldg(bp + col);
            const float b1 = __ldg(bp + col + 1);
            float2 v0 = make_float2(acc[mi][nj][0] + b0, acc[mi][nj][1] + b1);
            float2 v1 = make_float2(acc[mi][nj][2] + b0, acc[mi][nj][3] + b1);
            *reinterpret_cast<float2*>(out + (size_t)r0 * N_DIM + col) = v0;
            *reinterpret_cast<float2*>(out + (size_t)(r0 + 8) * N_DIM + col) = v1;
        }
    }
}

extern "C" void kernel_launch(void* const* d_in, const int* in_sizes, int n_in,
                              void* d_out, int out_size) {
    const float* x      = (const float*)d_in[0];  // [8,512,1024]
    const float* W      = (const float*)d_in[1];  // [8,1024,1024]
    const float* b      = (const float*)d_in[2];  // [8,1024]
    const float* logits = (const float*)d_in[3];  // [8]
    const float* u      = (const float*)d_in[4];  // [8]
    float* out          = (float*)d_out;          // [8,512,1024]

    cudaFuncSetAttribute(mixed_op_hmma_kernel,
                         cudaFuncAttributeMaxDynamicSharedMemorySize, SMEM_TOTAL);

    dim3 grid(N_DIM / BN, M_DIM / BM);  // (8, 32)
    mixed_op_hmma_kernel<<<grid, 256, SMEM_TOTAL>>>(x, W, b, logits, u, out);
}